// round 1
// baseline (speedup 1.0000x reference)
#include <cuda_runtime.h>

// Problem dims (fixed per reference setup_inputs)
#define T_STEPS 64
#define BATCH   512
#define IN_DIM  784
#define HID     2048
#define OUT_DIM 10
#define M_TOT   (T_STEPS * BATCH)   // 32768

// ---------------- scratch (device globals; no cudaMalloc allowed) -----------
__device__ float g_cur[(size_t)M_TOT * HID];      // 256 MiB: CUR[t*B+b][h]
__device__ float g_woutT[HID * OUT_DIM];          // w_out transposed [HID][10]

// ---------------- tiny transpose: w_out [10,2048] -> [2048,10] --------------
__global__ void transpose_wout_kernel(const float* __restrict__ wout) {
    int i = blockIdx.x * blockDim.x + threadIdx.x;
    if (i < HID * OUT_DIM) {
        int o = i / HID;
        int h = i % HID;
        g_woutT[h * OUT_DIM + o] = wout[i];
    }
}

// ---------------- SGEMM: C[m][n] = sum_k A[m][k] * B[n][k] ------------------
// A = x reshaped [32768, 784], B = w1 [2048, 784]. Both K-contiguous (NT).
// Tiles: BM=128, BN=128, BK=16; 256 threads; 8x8 per-thread microtile.
#define BM 128
#define BN 128
#define BK 16
#define TM 8
#define TN 8

__global__ __launch_bounds__(256, 2)
void sgemm_nt_kernel(const float* __restrict__ A, const float* __restrict__ B) {
    __shared__ float As[BK][BM];
    __shared__ float Bs[BK][BN];

    const int tid = threadIdx.x;
    const int bn  = blockIdx.x;   // 0..15   (N/BN)
    const int bm  = blockIdx.y;   // 0..255  (M/BM)

    const float* Ab = A + (size_t)bm * BM * IN_DIM;
    const float* Bb = B + (size_t)bn * BN * IN_DIM;
    float* Cb = g_cur + (size_t)bm * BM * HID + (size_t)bn * BN;

    // Load mapping: 128 rows x 4 float4-chunks = 512 float4; 2 per thread.
    const int lrow = tid >> 2;          // 0..63
    const int lkc  = (tid & 3) * 4;     // 0,4,8,12

    const int ty = tid >> 4;            // 0..15 -> row group
    const int tx = tid & 15;            // 0..15 -> col group

    float acc[TM][TN];
    #pragma unroll
    for (int i = 0; i < TM; ++i)
        #pragma unroll
        for (int j = 0; j < TN; ++j) acc[i][j] = 0.0f;

    for (int k0 = 0; k0 < IN_DIM; k0 += BK) {
        // stage A and B tiles (transposed into [k][m] layout)
        #pragma unroll
        for (int h = 0; h < 2; ++h) {
            int r = lrow + h * 64;
            float4 va = *(const float4*)(Ab + (size_t)r * IN_DIM + k0 + lkc);
            As[lkc + 0][r] = va.x;
            As[lkc + 1][r] = va.y;
            As[lkc + 2][r] = va.z;
            As[lkc + 3][r] = va.w;
            float4 vb = *(const float4*)(Bb + (size_t)r * IN_DIM + k0 + lkc);
            Bs[lkc + 0][r] = vb.x;
            Bs[lkc + 1][r] = vb.y;
            Bs[lkc + 2][r] = vb.z;
            Bs[lkc + 3][r] = vb.w;
        }
        __syncthreads();

        #pragma unroll
        for (int k = 0; k < BK; ++k) {
            float ra[TM], rb[TN];
            #pragma unroll
            for (int i = 0; i < TM; ++i) ra[i] = As[k][ty * TM + i];
            #pragma unroll
            for (int j = 0; j < TN; ++j) rb[j] = Bs[k][tx * TN + j];
            #pragma unroll
            for (int i = 0; i < TM; ++i)
                #pragma unroll
                for (int j = 0; j < TN; ++j)
                    acc[i][j] = fmaf(ra[i], rb[j], acc[i][j]);
        }
        __syncthreads();
    }

    // write out 8x8 per thread (two float4 per row)
    #pragma unroll
    for (int i = 0; i < TM; ++i) {
        float* crow = Cb + (size_t)(ty * TM + i) * HID + tx * TN;
        float4 v0 = make_float4(acc[i][0], acc[i][1], acc[i][2], acc[i][3]);
        float4 v1 = make_float4(acc[i][4], acc[i][5], acc[i][6], acc[i][7]);
        *(float4*)(crow + 0) = v0;
        *(float4*)(crow + 4) = v1;
    }
}

// ---------------- persistent per-batch scan ---------------------------------
// One block per batch element b. State (v1,i1) lives in registers across all
// 64 timesteps; per-step spike-gated readout reduced with warp shuffles.
#define SCAN_THREADS 256
#define UPT (HID / SCAN_THREADS)   // 8 hidden units per thread

__global__ __launch_bounds__(SCAN_THREADS, 2)
void scan_kernel(float* __restrict__ out) {
    const int b   = blockIdx.x;
    const int tid = threadIdx.x;

    float v1[UPT], i1[UPT];
    float w[UPT][OUT_DIM];
    #pragma unroll
    for (int j = 0; j < UPT; ++j) {
        v1[j] = 0.0f;
        i1[j] = 0.0f;
        int h = tid + j * SCAN_THREADS;
        #pragma unroll
        for (int o = 0; o < OUT_DIM; ++o) w[j][o] = g_woutT[h * OUT_DIM + o];
    }

    // readout state: held in registers of threads 0..9
    float vo = 0.0f, io = 0.0f, vmax = -1e30f;

    __shared__ float red[SCAN_THREADS / 32][OUT_DIM];

    for (int t = 0; t < T_STEPS; ++t) {
        const float* crow = g_cur + ((size_t)t * BATCH + b) * HID;

        float acc[OUT_DIM];
        #pragma unroll
        for (int o = 0; o < OUT_DIM; ++o) acc[o] = 0.0f;

        #pragma unroll
        for (int j = 0; j < UPT; ++j) {
            int h = tid + j * SCAN_THREADS;
            float c  = crow[h];
            // v1_dec = v1 + 0.1*(i1 - v1); i1_dec = i1 * 0.8
            float vd = v1[j] + 0.1f * (i1[j] - v1[j]);
            float id = i1[j] * 0.8f;
            float z  = (vd - 0.5f) > 0.0f ? 1.0f : 0.0f;
            v1[j] = (1.0f - z) * vd;
            i1[j] = id + c;
            if (z != 0.0f) {
                #pragma unroll
                for (int o = 0; o < OUT_DIM; ++o) acc[o] += w[j][o];
            }
        }

        // intra-warp reduce
        #pragma unroll
        for (int o = 0; o < OUT_DIM; ++o) {
            #pragma unroll
            for (int s = 16; s > 0; s >>= 1)
                acc[o] += __shfl_xor_sync(0xffffffffu, acc[o], s);
        }
        int warp = tid >> 5, lane = tid & 31;
        if (lane == 0) {
            #pragma unroll
            for (int o = 0; o < OUT_DIM; ++o) red[warp][o] = acc[o];
        }
        __syncthreads();

        if (tid < OUT_DIM) {
            float s = 0.0f;
            #pragma unroll
            for (int wp = 0; wp < SCAN_THREADS / 32; ++wp) s += red[wp][tid];
            // LI readout: vo_new uses OLD io (reference ordering)
            float vn = vo + 0.1f * (io - vo);
            io = io * 0.8f + s;
            vo = vn;
            vmax = fmaxf(vmax, vn);
        }
        __syncthreads();
    }

    if (tid < OUT_DIM) out[b * OUT_DIM + tid] = vmax;
}

// ---------------- launch ------------------------------------------------------
extern "C" void kernel_launch(void* const* d_in, const int* in_sizes, int n_in,
                              void* d_out, int out_size) {
    const float* x    = (const float*)d_in[0];  // [64,512,1,28,28] = [32768,784]
    const float* w1   = (const float*)d_in[1];  // [2048,784]
    const float* wout = (const float*)d_in[2];  // [10,2048]
    float* out = (float*)d_out;                 // [512,10]

    transpose_wout_kernel<<<(HID * OUT_DIM + 255) / 256, 256>>>(wout);

    dim3 ggrid(HID / BN, M_TOT / BM);           // (16, 256)
    sgemm_nt_kernel<<<ggrid, 256>>>(x, w1);

    scan_kernel<<<BATCH, SCAN_THREADS>>>(out);
}